// round 1
// baseline (speedup 1.0000x reference)
#include <cuda_runtime.h>
#include <cuda_bf16.h>
#include <math.h>

#define BATCH 1024
#define NC 32
#define LPRE 1041
#define LH 520
#define L1 257
#define L2 125
#define LP 31
#define LZ 12

// ---------------- scratch (device globals; no allocation in kernel_launch) ----------
__device__ float g_filt[NC * 16];
__device__ float g_hpre[BATCH * NC * LPRE];       // 136 MB
__device__ float g_h[BATCH * NC * LH];            // 68 MB
__device__ float g_p1[BATCH * NC * LP];
__device__ float g_p2[BATCH * NC * LP];
__device__ float g_psum[NC * 64];
__device__ float g_psq[NC * 64];
__device__ float g_mean1[NC], g_rstd1[NC];
__device__ float g_mean2[NC], g_rstd2[NC];
__device__ float g_mean3[NC], g_rstd3[NC];
__device__ float g_z[BATCH * 768];
__device__ float g_z1[BATCH * 1024];
__device__ float g_z2[BATCH * 512];
__device__ float g_z3[BATCH * 128];

// ---------------- 1. Laplace filter bank --------------------------------------------
__global__ void k_filt(const float* __restrict__ la_a, const float* __restrict__ la_b) {
    int t = threadIdx.x;
    if (t >= NC * 16) return;
    int c = t >> 4, k = t & 15;
    const float wf = 314.1592653589793f;          // 2*pi*50, cast to f32 like JAX
    const float c1 = (float)(-0.03 / sqrt(1.0 - 0.03 * 0.03));
    float tt = (float)k / 15.0f;
    float p = tt - la_b[c] / la_a[c];
    float arg = wf * (p - 0.1f);
    g_filt[t] = 0.08f * expf(c1 * arg) * (-sinf(arg));
}

// ---------------- 2. conv1d (pad 16,16) + bias -> hpre ------------------------------
__global__ void __launch_bounds__(256) k_conv(const float* __restrict__ x,
                                              const float* __restrict__ la_bias) {
    __shared__ float sx[143];
    __shared__ float sf[NC * 16];
    __shared__ float sb[NC];
    int b = blockIdx.y;
    int t0 = blockIdx.x * 128;
    int t = threadIdx.x;
    for (int i = t; i < NC * 16; i += 256) sf[i] = g_filt[i];
    if (t < NC) sb[t] = la_bias[t];
    for (int i = t; i < 143; i += 256) {
        int xi = t0 - 16 + i;
        sx[i] = (xi >= 0 && xi < 1024) ? x[b * 1024 + xi] : 0.0f;
    }
    __syncthreads();
    int l = t & 31, w = t >> 5;                   // lane, warp(0..7)
    for (int r = 0; r < 4; r++) {
        int c = w * 4 + r;
        float bias = sb[c];
        const float* fw = &sf[c * 16];
        for (int q = 0; q < 4; q++) {
            int pos = l + 32 * q;
            int opos = t0 + pos;
            if (opos < LPRE) {
                float acc = bias;
#pragma unroll
                for (int k = 0; k < 16; k++) acc += sx[pos + k] * fw[k];
                g_hpre[(b * NC + c) * LPRE + opos] = acc;
            }
        }
    }
}

// ---------------- 3. BN1 stats (two-level deterministic reduction) ------------------
__global__ void __launch_bounds__(256) k_stats1_part() {
    int chunk = blockIdx.x;   // 0..63 (16 batch rows each)
    int c = blockIdx.y;
    int t = threadIdx.x;
    float s = 0.0f, sq = 0.0f;
    for (int bb = 0; bb < 16; bb++) {
        const float* row = &g_hpre[((chunk * 16 + bb) * NC + c) * LPRE];
        for (int i = t; i < LPRE; i += 256) {
            float v = row[i];
            s += v; sq += v * v;
        }
    }
    __shared__ float ss[256], ssq[256];
    ss[t] = s; ssq[t] = sq;
    __syncthreads();
    for (int o = 128; o > 0; o >>= 1) {
        if (t < o) { ss[t] += ss[t + o]; ssq[t] += ssq[t + o]; }
        __syncthreads();
    }
    if (t == 0) { g_psum[c * 64 + chunk] = ss[0]; g_psq[c * 64 + chunk] = ssq[0]; }
}

__global__ void k_stats1_fin() {
    int c = blockIdx.x, t = threadIdx.x;   // 64 threads
    __shared__ float ss[64], ssq[64];
    ss[t] = g_psum[c * 64 + t];
    ssq[t] = g_psq[c * 64 + t];
    __syncthreads();
    for (int o = 32; o > 0; o >>= 1) {
        if (t < o) { ss[t] += ss[t + o]; ssq[t] += ssq[t + o]; }
        __syncthreads();
    }
    if (t == 0) {
        float n = (float)BATCH * (float)LPRE;
        float m = ss[0] / n;
        float v = ssq[0] / n - m * m;
        g_mean1[c] = m;
        g_rstd1[c] = rsqrtf(v + 1e-5f);
    }
}

// ---------------- 4. apply BN1 + avgpool(3,2) -> h ----------------------------------
__global__ void __launch_bounds__(256) k_bnpool(const float* __restrict__ g1,
                                                const float* __restrict__ b1) {
    int idx = blockIdx.x * blockDim.x + threadIdx.x;
    const int total = BATCH * NC * LH;
    if (idx >= total) return;
    int i = idx % LH;
    int bc = idx / LH;
    int c = bc & (NC - 1);
    const float* row = &g_hpre[bc * LPRE + 2 * i];
    float scale = g_rstd1[c] * g1[c];
    float shift = b1[c] - g_mean1[c] * scale;
    float v = (row[0] + row[1] + row[2]) * (1.0f / 3.0f);
    g_h[idx] = v * scale + shift;
}

// ---------------- 5. branch stage 1: conv8s2 -> conv8s2 -> maxpool(4,4) -------------
// mode 0 = always  (bias' = b - sum w),  mode 1 = eventually (bias' = 1 - b)
__global__ void __launch_bounds__(256) k_stage1(int branch,
                                                const float* __restrict__ w1, const float* __restrict__ b1, int mode1,
                                                const float* __restrict__ w2, const float* __restrict__ b2, int mode2) {
    int bc = blockIdx.x;
    int c = bc & (NC - 1);
    int t = threadIdx.x;
    __shared__ float sh[LH];
    __shared__ float sa[L1];
    __shared__ float se[L2];
    for (int i = t; i < LH; i += 256) sh[i] = g_h[bc * LH + i];
    float wA[8], wB[8];
#pragma unroll
    for (int k = 0; k < 8; k++) { wA[k] = w1[c * 8 + k]; wB[k] = w2[c * 8 + k]; }
    float biasA, biasB;
    if (mode1 == 0) { float sw = 0; for (int k = 0; k < 8; k++) sw += wA[k]; biasA = b1[c] - sw; }
    else            { biasA = 1.0f - b1[c]; }
    if (mode2 == 0) { float sw = 0; for (int k = 0; k < 8; k++) sw += wB[k]; biasB = b2[c] - sw; }
    else            { biasB = 1.0f - b2[c]; }
    __syncthreads();
    for (int i = t; i < L1; i += 256) {
        float a = biasA;
#pragma unroll
        for (int k = 0; k < 8; k++) a += sh[2 * i + k] * wA[k];
        sa[i] = fmaxf(a, 0.0f);
    }
    __syncthreads();
    if (t < L2) {
        float a = biasB;
#pragma unroll
        for (int k = 0; k < 8; k++) a += sa[2 * t + k] * wB[k];
        se[t] = fmaxf(a, 0.0f);
    }
    __syncthreads();
    if (t < LP) {
        float m = se[4 * t];
#pragma unroll
        for (int j = 1; j < 4; j++) m = fmaxf(m, se[4 * t + j]);
        float* pout = (branch == 0) ? g_p1 : g_p2;
        pout[bc * LP + t] = m;
    }
}

// ---------------- 6. BN2/BN3 stats --------------------------------------------------
__global__ void __launch_bounds__(256) k_stats2(int branch) {
    int c = blockIdx.x, t = threadIdx.x;
    const float* p = (branch == 0) ? g_p1 : g_p2;
    const int n = BATCH * LP;
    float s = 0.0f, sq = 0.0f;
    for (int idx = t; idx < n; idx += 256) {
        int b = idx / LP;
        int i = idx - b * LP;
        float v = p[(b * NC + c) * LP + i];
        s += v; sq += v * v;
    }
    __shared__ float ss[256], ssq[256];
    ss[t] = s; ssq[t] = sq;
    __syncthreads();
    for (int o = 128; o > 0; o >>= 1) {
        if (t < o) { ss[t] += ss[t + o]; ssq[t] += ssq[t + o]; }
        __syncthreads();
    }
    if (t == 0) {
        float m = ss[0] / (float)n;
        float v = ssq[0] / (float)n - m * m;
        if (branch == 0) { g_mean2[c] = m; g_rstd2[c] = rsqrtf(v + 1e-5f); }
        else             { g_mean3[c] = m; g_rstd3[c] = rsqrtf(v + 1e-5f); }
    }
}

// ---------------- 7. apply BN + final eventually -> z -------------------------------
__global__ void __launch_bounds__(256) k_stage2(int branch,
                                                const float* __restrict__ g,
                                                const float* __restrict__ be,
                                                const float* __restrict__ w,
                                                const float* __restrict__ bb) {
    int bc = blockIdx.x * blockDim.x + threadIdx.x;
    if (bc >= BATCH * NC) return;
    int b = bc >> 5, c = bc & (NC - 1);
    const float* p;
    const float* meanv;
    const float* rstdv;
    int zbase;
    if (branch == 0) { p = g_p1; meanv = g_mean2; rstdv = g_rstd2; zbase = 0; }
    else             { p = g_p2; meanv = g_mean3; rstdv = g_rstd3; zbase = 384; }
    float sc = rstdv[c] * g[c];
    float sh = be[c] - meanv[c] * sc;
    float y[LP];
    const float* row = &p[bc * LP];
#pragma unroll
    for (int i = 0; i < LP; i++) y[i] = row[i] * sc + sh;
    float wv[8];
#pragma unroll
    for (int k = 0; k < 8; k++) wv[k] = w[c * 8 + k];
    float bias = 1.0f - bb[c];   // e2 / f2 are Eventually layers
#pragma unroll
    for (int j = 0; j < LZ; j++) {
        float acc = bias;
#pragma unroll
        for (int k = 0; k < 8; k++) acc += y[2 * j + k] * wv[k];
        g_z[b * 768 + zbase + c * LZ + j] = fmaxf(acc, 0.0f);
    }
}

// ---------------- 8. tiled fp32 GEMM + bias + relu ----------------------------------
// C(1024,N) = relu(A(1024,K) @ W(K,N) + bias). 64x64 tile, 4x4 per thread.
__global__ void __launch_bounds__(256) k_gemm(int stage, const float* __restrict__ W,
                                              const float* __restrict__ bias,
                                              float* dout, int K, int N) {
    const float* A;
    float* Cp;
    if (stage == 0)      { A = g_z;  Cp = g_z1; }
    else if (stage == 1) { A = g_z1; Cp = g_z2; }
    else if (stage == 2) { A = g_z2; Cp = g_z3; }
    else                 { A = g_z3; Cp = dout; }

    __shared__ float As[16][64];
    __shared__ float Bs[16][64];
    int tx = threadIdx.x & 15, ty = threadIdx.x >> 4;
    int m0 = blockIdx.y * 64, n0 = blockIdx.x * 64;
    float acc[4][4] = {};
    int am = threadIdx.x >> 2;          // 0..63
    int ak = (threadIdx.x & 3) * 4;     // 0,4,8,12
    int bk = threadIdx.x >> 4;          // 0..15
    int bn = (threadIdx.x & 15) * 4;

    for (int k0 = 0; k0 < K; k0 += 16) {
        const float* ap = &A[(m0 + am) * K + k0 + ak];
#pragma unroll
        for (int kk = 0; kk < 4; kk++) As[ak + kk][am] = ap[kk];
#pragma unroll
        for (int nn = 0; nn < 4; nn++) {
            int n = n0 + bn + nn;
            Bs[bk][bn + nn] = (n < N) ? W[(k0 + bk) * N + n] : 0.0f;
        }
        __syncthreads();
#pragma unroll
        for (int k = 0; k < 16; k++) {
            float av[4], bv[4];
#pragma unroll
            for (int i = 0; i < 4; i++) av[i] = As[k][ty * 4 + i];
#pragma unroll
            for (int j = 0; j < 4; j++) bv[j] = Bs[k][tx * 4 + j];
#pragma unroll
            for (int i = 0; i < 4; i++)
#pragma unroll
                for (int j = 0; j < 4; j++) acc[i][j] += av[i] * bv[j];
        }
        __syncthreads();
    }
#pragma unroll
    for (int i = 0; i < 4; i++) {
        int m = m0 + ty * 4 + i;
#pragma unroll
        for (int j = 0; j < 4; j++) {
            int n = n0 + tx * 4 + j;
            if (n < N) Cp[m * N + n] = fmaxf(acc[i][j] + bias[n], 0.0f);
        }
    }
}

// ---------------- host ---------------------------------------------------------------
extern "C" void kernel_launch(void* const* d_in, const int* in_sizes, int n_in,
                              void* d_out, int out_size) {
    const float* x       = (const float*)d_in[0];
    const float* la_a    = (const float*)d_in[1];
    const float* la_b    = (const float*)d_in[2];
    const float* la_bias = (const float*)d_in[3];
    const float* bn1_g   = (const float*)d_in[4];
    const float* bn1_b   = (const float*)d_in[5];
    const float* a1_w = (const float*)d_in[6];
    const float* a1_b = (const float*)d_in[7];
    const float* e1_w = (const float*)d_in[8];
    const float* e1_b = (const float*)d_in[9];
    const float* bn2_g = (const float*)d_in[10];
    const float* bn2_b = (const float*)d_in[11];
    const float* e2_w = (const float*)d_in[12];
    const float* e2_b = (const float*)d_in[13];
    const float* f1_w = (const float*)d_in[14];
    const float* f1_b = (const float*)d_in[15];
    const float* fa_w = (const float*)d_in[16];
    const float* fa_b = (const float*)d_in[17];
    const float* bn3_g = (const float*)d_in[18];
    const float* bn3_b = (const float*)d_in[19];
    const float* f2_w = (const float*)d_in[20];
    const float* f2_b = (const float*)d_in[21];
    const float* w1 = (const float*)d_in[22];
    const float* b1 = (const float*)d_in[23];
    const float* w2 = (const float*)d_in[24];
    const float* b2 = (const float*)d_in[25];
    const float* w3 = (const float*)d_in[26];
    const float* b3 = (const float*)d_in[27];
    const float* w4 = (const float*)d_in[28];
    const float* b4 = (const float*)d_in[29];
    float* out = (float*)d_out;

    k_filt<<<1, 512>>>(la_a, la_b);
    k_conv<<<dim3(9, BATCH), 256>>>(x, la_bias);
    k_stats1_part<<<dim3(64, NC), 256>>>();
    k_stats1_fin<<<NC, 64>>>();
    {
        int total = BATCH * NC * LH;
        k_bnpool<<<(total + 255) / 256, 256>>>(bn1_g, bn1_b);
    }
    k_stage1<<<BATCH * NC, 256>>>(0, a1_w, a1_b, 0, e1_w, e1_b, 1);
    k_stage1<<<BATCH * NC, 256>>>(1, f1_w, f1_b, 1, fa_w, fa_b, 0);
    k_stats2<<<NC, 256>>>(0);
    k_stats2<<<NC, 256>>>(1);
    k_stage2<<<(BATCH * NC + 255) / 256, 256>>>(0, bn2_g, bn2_b, e2_w, e2_b);
    k_stage2<<<(BATCH * NC + 255) / 256, 256>>>(1, bn3_g, bn3_b, f2_w, f2_b);

    k_gemm<<<dim3(16, 16), 256>>>(0, w1, b1, nullptr, 768, 1024);
    k_gemm<<<dim3(8, 16),  256>>>(1, w2, b2, nullptr, 1024, 512);
    k_gemm<<<dim3(2, 16),  256>>>(2, w3, b3, nullptr, 512, 128);
    k_gemm<<<dim3(1, 16),  256>>>(3, w4, b4, out, 128, 10);
}

// round 3
// speedup vs baseline: 1.8417x; 1.8417x over previous
#include <cuda_runtime.h>
#include <cuda_bf16.h>
#include <math.h>

#define BATCH 1024
#define NC 32
#define LPRE 1041
#define LH 520
#define L1 257
#define L2 125
#define LP 31
#define LZ 12

// ---------------- scratch (device globals) ------------------------------------------
__device__ float g_filt[NC * 16];
__device__ float g_h[BATCH * NC * LH];            // pooled RAW conv (pre-BN), 68 MB
__device__ float g_p1[BATCH * NC * LP];
__device__ float g_p2[BATCH * NC * LP];
__device__ float g_psA[NC * BATCH];               // BN1 partial sums (per b)
__device__ float g_psqA[NC * BATCH];
__device__ float g_ps2[2 * NC * BATCH];           // BN2/BN3 partials
__device__ float g_psq2[2 * NC * BATCH];
__device__ float g_mean1[NC], g_rstd1[NC];
__device__ float g_mean2[NC], g_rstd2[NC];
__device__ float g_mean3[NC], g_rstd3[NC];
__device__ float g_z[BATCH * 768];
__device__ float g_z1[BATCH * 1024];
__device__ float g_z2[BATCH * 512];
__device__ float g_z3[BATCH * 128];

// ---------------- 1. Laplace filter bank --------------------------------------------
__global__ void k_filt(const float* __restrict__ la_a, const float* __restrict__ la_b) {
    int t = threadIdx.x;
    if (t >= NC * 16) return;
    int c = t >> 4, k = t & 15;
    const float wf = 314.1592653589793f;
    const float c1 = (float)(-0.03 / sqrt(1.0 - 0.03 * 0.03));
    float tt = (float)k / 15.0f;
    float p = tt - la_b[c] / la_a[c];
    float arg = wf * (p - 0.1f);
    g_filt[t] = 0.08f * expf(c1 * arg) * (-sinf(arg));
}

// ---------------- 2. fused conv + bias + BN1 partial stats + avgpool(3,2) -----------
#define SROW_STRIDE 1048
__global__ void __launch_bounds__(256) k_convfuse(const float* __restrict__ x,
                                                  const float* __restrict__ la_bias) {
    __shared__ float sx[1072];               // x padded by 16 on each side
    __shared__ float sf[NC * 16];
    __shared__ float sb[NC];
    __shared__ float srow[8 * SROW_STRIDE];  // one conv row per warp
    int b = blockIdx.x;
    int t = threadIdx.x;
    int l = t & 31, w = t >> 5;
    for (int i = t; i < NC * 16; i += 256) sf[i] = g_filt[i];
    if (t < NC) sb[t] = la_bias[t];
    for (int i = t; i < 1072; i += 256) {
        int xi = i - 16;
        sx[i] = (xi >= 0 && xi < 1024) ? x[b * 1024 + xi] : 0.0f;
    }
    __syncthreads();

    float* my = &srow[w * SROW_STRIDE];
    for (int r = 0; r < 4; r++) {
        int c = w * 4 + r;
        float fw[16];
#pragma unroll
        for (int k = 0; k < 16; k++) fw[k] = sf[c * 16 + k];
        float bias = sb[c];
        float s = 0.0f, sq = 0.0f;
        for (int j = 0; j < 9; j++) {
            int o0 = 4 * l + 128 * j;
            if (o0 > 1040) break;
            float xw[20];
#pragma unroll
            for (int q = 0; q < 5; q++) {
                float4 v = *(const float4*)&sx[o0 + 4 * q];
                xw[4 * q + 0] = v.x; xw[4 * q + 1] = v.y; xw[4 * q + 2] = v.z; xw[4 * q + 3] = v.w;
            }
            float4 ov;
            float* op = (float*)&ov;
#pragma unroll
            for (int q = 0; q < 4; q++) {
                float acc = bias;
#pragma unroll
                for (int k = 0; k < 16; k++) acc += xw[q + k] * fw[k];
                op[q] = acc;
                if (o0 + q < LPRE) { s += acc; sq += acc * acc; }
            }
            *(float4*)&my[o0] = ov;
        }
        __syncwarp();
        for (int i = l; i < LH; i += 32) {
            float v = (my[2 * i] + my[2 * i + 1] + my[2 * i + 2]) * (1.0f / 3.0f);
            g_h[(b * NC + c) * LH + i] = v;
        }
#pragma unroll
        for (int off = 16; off > 0; off >>= 1) {
            s  += __shfl_down_sync(0xffffffffu, s, off);
            sq += __shfl_down_sync(0xffffffffu, sq, off);
        }
        if (l == 0) { g_psA[c * BATCH + b] = s; g_psqA[c * BATCH + b] = sq; }
        __syncwarp();
    }
}

// ---------------- 3. BN1 finalize ---------------------------------------------------
__global__ void __launch_bounds__(256) k_fin1() {
    int c = blockIdx.x, t = threadIdx.x;
    float s = 0.0f, sq = 0.0f;
    for (int i = t; i < BATCH; i += 256) { s += g_psA[c * BATCH + i]; sq += g_psqA[c * BATCH + i]; }
    __shared__ float ss[256], ssq[256];
    ss[t] = s; ssq[t] = sq;
    __syncthreads();
    for (int o = 128; o > 0; o >>= 1) {
        if (t < o) { ss[t] += ss[t + o]; ssq[t] += ssq[t + o]; }
        __syncthreads();
    }
    if (t == 0) {
        float n = (float)BATCH * (float)LPRE;
        float m = ss[0] / n;
        float v = ssq[0] / n - m * m;
        g_mean1[c] = m;
        g_rstd1[c] = rsqrtf(v + 1e-5f);
    }
}

// ---------------- 4. both branches stage1 -------------------------------------------
__global__ void __launch_bounds__(256) k_branches(
        const float* __restrict__ bn1_g, const float* __restrict__ bn1_b,
        const float* __restrict__ a1_w, const float* __restrict__ a1_b,
        const float* __restrict__ e1_w, const float* __restrict__ e1_b,
        const float* __restrict__ f1_w, const float* __restrict__ f1_b,
        const float* __restrict__ fa_w, const float* __restrict__ fa_b) {
    __shared__ float sh[16 * LH];
    __shared__ float sa[8][260];
    __shared__ float se[8][128];
    int b = blockIdx.x >> 1;
    int c0 = (blockIdx.x & 1) * 16;
    int t = threadIdx.x;
    int l = t & 31, w = t >> 5;
    for (int i = t; i < 16 * LH; i += 256) {
        int r = i / LH, col = i - r * LH;
        sh[i] = g_h[(b * NC + c0 + r) * LH + col];
    }
    __syncthreads();

    for (int u = 0; u < 2; u++) {
        int cc = c0 + w * 2 + u;
        const float* hrow = &sh[(w * 2 + u) * LH];
        float sc = g_rstd1[cc] * bn1_g[cc];
        float shv = bn1_b[cc] - g_mean1[cc] * sc;

        for (int br = 0; br < 2; br++) {
            float w1v[8], w2v[8];
            float bias1, bias2;
            if (br == 0) {
                float sw = 0.0f;
#pragma unroll
                for (int k = 0; k < 8; k++) { float wv = a1_w[cc * 8 + k]; w1v[k] = sc * wv; sw += wv; }
                bias1 = (a1_b[cc] - sw) + shv * sw;               // Always
#pragma unroll
                for (int k = 0; k < 8; k++) w2v[k] = e1_w[cc * 8 + k];
                bias2 = 1.0f - e1_b[cc];                          // Eventually
            } else {
                float sw = 0.0f;
#pragma unroll
                for (int k = 0; k < 8; k++) { float wv = f1_w[cc * 8 + k]; w1v[k] = sc * wv; sw += wv; }
                bias1 = (1.0f - f1_b[cc]) + shv * sw;             // Eventually
                float sw2 = 0.0f;
#pragma unroll
                for (int k = 0; k < 8; k++) { float wv = fa_w[cc * 8 + k]; w2v[k] = wv; sw2 += wv; }
                bias2 = fa_b[cc] - sw2;                           // Always
            }
            for (int i = l; i < L1; i += 32) {
                float a = bias1;
#pragma unroll
                for (int k = 0; k < 8; k++) a += hrow[2 * i + k] * w1v[k];
                sa[w][i] = fmaxf(a, 0.0f);
            }
            __syncwarp();
            for (int i = l; i < L2; i += 32) {
                float a = bias2;
#pragma unroll
                for (int k = 0; k < 8; k++) a += sa[w][2 * i + k] * w2v[k];
                se[w][i] = fmaxf(a, 0.0f);
            }
            __syncwarp();
            float s = 0.0f, sq = 0.0f;
            if (l < LP) {
                float m = se[w][4 * l];
#pragma unroll
                for (int j = 1; j < 4; j++) m = fmaxf(m, se[w][4 * l + j]);
                float* pout = (br == 0) ? g_p1 : g_p2;
                pout[(b * NC + cc) * LP + l] = m;
                s = m; sq = m * m;
            }
#pragma unroll
            for (int off = 16; off > 0; off >>= 1) {
                s  += __shfl_down_sync(0xffffffffu, s, off);
                sq += __shfl_down_sync(0xffffffffu, sq, off);
            }
            if (l == 0) {
                g_ps2[(br * NC + cc) * BATCH + b] = s;
                g_psq2[(br * NC + cc) * BATCH + b] = sq;
            }
            __syncwarp();
        }
    }
}

// ---------------- 5. BN2/BN3 finalize -----------------------------------------------
__global__ void __launch_bounds__(256) k_fin2() {
    int bc = blockIdx.x;   // 0..63 : branch*32 + c
    int t = threadIdx.x;
    float s = 0.0f, sq = 0.0f;
    for (int i = t; i < BATCH; i += 256) { s += g_ps2[bc * BATCH + i]; sq += g_psq2[bc * BATCH + i]; }
    __shared__ float ss[256], ssq[256];
    ss[t] = s; ssq[t] = sq;
    __syncthreads();
    for (int o = 128; o > 0; o >>= 1) {
        if (t < o) { ss[t] += ss[t + o]; ssq[t] += ssq[t + o]; }
        __syncthreads();
    }
    if (t == 0) {
        float n = (float)BATCH * (float)LP;
        float m = ss[0] / n;
        float v = ssq[0] / n - m * m;
        int br = bc >> 5, c = bc & 31;
        if (br == 0) { g_mean2[c] = m; g_rstd2[c] = rsqrtf(v + 1e-5f); }
        else         { g_mean3[c] = m; g_rstd3[c] = rsqrtf(v + 1e-5f); }
    }
}

// ---------------- 6. BN + final eventually -> z -------------------------------------
__global__ void __launch_bounds__(256) k_stage2(int branch,
                                                const float* __restrict__ g,
                                                const float* __restrict__ be,
                                                const float* __restrict__ w,
                                                const float* __restrict__ bb) {
    int bc = blockIdx.x * blockDim.x + threadIdx.x;
    if (bc >= BATCH * NC) return;
    int b = bc >> 5, c = bc & (NC - 1);
    const float* p;
    const float* meanv;
    const float* rstdv;
    int zbase;
    if (branch == 0) { p = g_p1; meanv = g_mean2; rstdv = g_rstd2; zbase = 0; }
    else             { p = g_p2; meanv = g_mean3; rstdv = g_rstd3; zbase = 384; }
    float sc = rstdv[c] * g[c];
    float sh = be[c] - meanv[c] * sc;
    float wv[8];
    float sw = 0.0f;
#pragma unroll
    for (int k = 0; k < 8; k++) { wv[k] = w[c * 8 + k] * sc; sw += w[c * 8 + k]; }
    float bias = (1.0f - bb[c]) + sh * sw;   // Eventually with BN folded
    float y[LP];
    const float* row = &p[bc * LP];
#pragma unroll
    for (int i = 0; i < LP; i++) y[i] = row[i];
#pragma unroll
    for (int j = 0; j < LZ; j++) {
        float acc = bias;
#pragma unroll
        for (int k = 0; k < 8; k++) acc += y[2 * j + k] * wv[k];
        g_z[b * 768 + zbase + c * LZ + j] = fmaxf(acc, 0.0f);
    }
}

// ---------------- 7. tiled fp32 GEMM + bias + relu ----------------------------------
// stage selects A/C from device globals INSIDE device code (host cannot pass
// __device__ array addresses as kernel args — that was the round-2 bug).
template<int BM, int BN, int BK, int TM, int TN>
__global__ void __launch_bounds__(256) k_gemm_t(int stage,
                                                const float* __restrict__ W,
                                                const float* __restrict__ bias,
                                                int K, int N) {
    const float* A;
    float* C;
    if (stage == 0)      { A = g_z;  C = g_z1; }
    else if (stage == 1) { A = g_z1; C = g_z2; }
    else                 { A = g_z2; C = g_z3; }

    __shared__ float As[BK * BM];
    __shared__ float Bs[BK * BN];
    constexpr int TX = BN / TN;
    int tid = threadIdx.x;
    int tx = tid % TX, ty = tid / TX;
    int m0 = blockIdx.y * BM, n0 = blockIdx.x * BN;
    float acc[TM][TN] = {};
    for (int k0 = 0; k0 < K; k0 += BK) {
        for (int idx = tid * 4; idx < BM * BK; idx += 1024) {
            int m = idx / BK, kq = idx % BK;
            float4 v = *(const float4*)(A + (m0 + m) * K + k0 + kq);
            As[(kq + 0) * BM + m] = v.x;
            As[(kq + 1) * BM + m] = v.y;
            As[(kq + 2) * BM + m] = v.z;
            As[(kq + 3) * BM + m] = v.w;
        }
        for (int idx = tid * 4; idx < BK * BN; idx += 1024) {
            int k = idx / BN, n = idx % BN;
            *(float4*)&Bs[k * BN + n] = *(const float4*)(W + (k0 + k) * N + n0 + n);
        }
        __syncthreads();
#pragma unroll
        for (int k = 0; k < BK; k++) {
            float av[TM], bv[TN];
#pragma unroll
            for (int i = 0; i < TM; i += 4) {
                float4 v = *(const float4*)&As[k * BM + ty * TM + i];
                av[i] = v.x; av[i + 1] = v.y; av[i + 2] = v.z; av[i + 3] = v.w;
            }
#pragma unroll
            for (int j = 0; j < TN; j++) bv[j] = Bs[k * BN + tx * TN + j];
#pragma unroll
            for (int i = 0; i < TM; i++)
#pragma unroll
                for (int j = 0; j < TN; j++) acc[i][j] += av[i] * bv[j];
        }
        __syncthreads();
    }
#pragma unroll
    for (int i = 0; i < TM; i++) {
        int m = m0 + ty * TM + i;
#pragma unroll
        for (int j = 0; j < TN; j++) {
            int n = n0 + tx * TN + j;
            C[m * N + n] = fmaxf(acc[i][j] + bias[n], 0.0f);
        }
    }
}

// ---------------- 8. final tiny GEMM (K=128, N=10) ----------------------------------
__global__ void __launch_bounds__(256) k_gemm4(const float* __restrict__ W,
                                               const float* __restrict__ bias,
                                               float* __restrict__ out) {
    __shared__ float sw[128 * 10];
    __shared__ float sb[10];
    int t = threadIdx.x;
    for (int i = t; i < 1280; i += 256) sw[i] = W[i];
    if (t < 10) sb[t] = bias[t];
    __syncthreads();
    int idx = blockIdx.x * 256 + t;
    if (idx >= BATCH * 10) return;
    int m = idx / 10, n = idx % 10;
    const float* a = &g_z3[m * 128];
    float acc = sb[n];
#pragma unroll 16
    for (int k = 0; k < 128; k++) acc += a[k] * sw[k * 10 + n];
    out[idx] = fmaxf(acc, 0.0f);
}

// ---------------- host ---------------------------------------------------------------
extern "C" void kernel_launch(void* const* d_in, const int* in_sizes, int n_in,
                              void* d_out, int out_size) {
    const float* x       = (const float*)d_in[0];
    const float* la_a    = (const float*)d_in[1];
    const float* la_b    = (const float*)d_in[2];
    const float* la_bias = (const float*)d_in[3];
    const float* bn1_g   = (const float*)d_in[4];
    const float* bn1_b   = (const float*)d_in[5];
    const float* a1_w = (const float*)d_in[6];
    const float* a1_b = (const float*)d_in[7];
    const float* e1_w = (const float*)d_in[8];
    const float* e1_b = (const float*)d_in[9];
    const float* bn2_g = (const float*)d_in[10];
    const float* bn2_b = (const float*)d_in[11];
    const float* e2_w = (const float*)d_in[12];
    const float* e2_b = (const float*)d_in[13];
    const float* f1_w = (const float*)d_in[14];
    const float* f1_b = (const float*)d_in[15];
    const float* fa_w = (const float*)d_in[16];
    const float* fa_b = (const float*)d_in[17];
    const float* bn3_g = (const float*)d_in[18];
    const float* bn3_b = (const float*)d_in[19];
    const float* f2_w = (const float*)d_in[20];
    const float* f2_b = (const float*)d_in[21];
    const float* w1 = (const float*)d_in[22];
    const float* b1 = (const float*)d_in[23];
    const float* w2 = (const float*)d_in[24];
    const float* b2 = (const float*)d_in[25];
    const float* w3 = (const float*)d_in[26];
    const float* b3 = (const float*)d_in[27];
    const float* w4 = (const float*)d_in[28];
    const float* b4 = (const float*)d_in[29];
    float* out = (float*)d_out;

    k_filt<<<1, 512>>>(la_a, la_b);
    k_convfuse<<<BATCH, 256>>>(x, la_bias);
    k_fin1<<<NC, 256>>>();
    k_branches<<<BATCH * 2, 256>>>(bn1_g, bn1_b, a1_w, a1_b, e1_w, e1_b,
                                   f1_w, f1_b, fa_w, fa_b);
    k_fin2<<<2 * NC, 256>>>();
    k_stage2<<<(BATCH * NC + 255) / 256, 256>>>(0, bn2_g, bn2_b, e2_w, e2_b);
    k_stage2<<<(BATCH * NC + 255) / 256, 256>>>(1, bn3_g, bn3_b, f2_w, f2_b);

    // z(1024,768) @ w1(768,1024) -> z1
    k_gemm_t<128, 64, 16, 8, 4><<<dim3(16, 8), 256>>>(0, w1, b1, 768, 1024);
    // z1 @ w2(1024,512) -> z2
    k_gemm_t<64, 64, 16, 4, 4><<<dim3(8, 16), 256>>>(1, w2, b2, 1024, 512);
    // z2 @ w3(512,128) -> z3
    k_gemm_t<64, 32, 16, 4, 2><<<dim3(4, 16), 256>>>(2, w3, b3, 512, 128);
    // z3 @ w4(128,10) -> out
    k_gemm4<<<40, 256>>>(w4, b4, out);
}

// round 4
// speedup vs baseline: 2.2825x; 1.2393x over previous
#include <cuda_runtime.h>
#include <cuda_bf16.h>
#include <math.h>
#include <stdint.h>

#define BATCH 1024
#define NC 32
#define LPRE 1041
#define LH 520
#define L1 257
#define L2 125
#define LP 31
#define LZ 12

// ---------------- scratch (device globals) ------------------------------------------
__device__ float g_filt[NC * 16];
__device__ float g_h[BATCH * NC * LH];            // pooled RAW conv (pre-BN), 68 MB
__device__ float g_p1[BATCH * NC * LP];
__device__ float g_p2[BATCH * NC * LP];
__device__ float g_psA[NC * BATCH];
__device__ float g_psqA[NC * BATCH];
__device__ float g_ps2[2 * NC * BATCH];
__device__ float g_psq2[2 * NC * BATCH];
__device__ float g_mean1[NC], g_rstd1[NC];
__device__ float g_mean2[NC], g_rstd2[NC];
__device__ float g_mean3[NC], g_rstd3[NC];
__device__ float g_z[BATCH * 768];
__device__ float g_z1[BATCH * 1024];
__device__ float g_z2[BATCH * 512];
__device__ float g_z3[BATCH * 128];

// ---------------- 1. Laplace filter bank --------------------------------------------
__global__ void k_filt(const float* __restrict__ la_a, const float* __restrict__ la_b) {
    int t = threadIdx.x;
    if (t >= NC * 16) return;
    int c = t >> 4, k = t & 15;
    const float wf = 314.1592653589793f;
    const float c1 = (float)(-0.03 / sqrt(1.0 - 0.03 * 0.03));
    float tt = (float)k / 15.0f;
    float p = tt - la_b[c] / la_a[c];
    float arg = wf * (p - 0.1f);
    g_filt[t] = 0.08f * expf(c1 * arg) * (-sinf(arg));
}

// ---------------- 2. fused conv + bias + BN1 partial stats + avgpool(3,2) -----------
#define SROW_STRIDE 1048
__global__ void __launch_bounds__(256) k_convfuse(const float* __restrict__ x,
                                                  const float* __restrict__ la_bias) {
    __shared__ float sx[1072];
    __shared__ float sf[NC * 16];
    __shared__ float sb[NC];
    __shared__ float srow[8 * SROW_STRIDE];
    int b = blockIdx.x;
    int t = threadIdx.x;
    int l = t & 31, w = t >> 5;
    for (int i = t; i < NC * 16; i += 256) sf[i] = g_filt[i];
    if (t < NC) sb[t] = la_bias[t];
    for (int i = t; i < 1072; i += 256) {
        int xi = i - 16;
        sx[i] = (xi >= 0 && xi < 1024) ? x[b * 1024 + xi] : 0.0f;
    }
    __syncthreads();

    float* my = &srow[w * SROW_STRIDE];
    for (int r = 0; r < 4; r++) {
        int c = w * 4 + r;
        float fw[16];
#pragma unroll
        for (int k = 0; k < 16; k++) fw[k] = sf[c * 16 + k];
        float bias = sb[c];
        float s = 0.0f, sq = 0.0f;
        for (int j = 0; j < 9; j++) {
            int o0 = 4 * l + 128 * j;
            if (o0 > 1040) break;
            float xw[20];
#pragma unroll
            for (int q = 0; q < 5; q++) {
                float4 v = *(const float4*)&sx[o0 + 4 * q];
                xw[4 * q + 0] = v.x; xw[4 * q + 1] = v.y; xw[4 * q + 2] = v.z; xw[4 * q + 3] = v.w;
            }
            float4 ov;
            float* op = (float*)&ov;
#pragma unroll
            for (int q = 0; q < 4; q++) {
                float acc = bias;
#pragma unroll
                for (int k = 0; k < 16; k++) acc += xw[q + k] * fw[k];
                op[q] = acc;
                if (o0 + q < LPRE) { s += acc; sq += acc * acc; }
            }
            *(float4*)&my[o0] = ov;
        }
        __syncwarp();
        for (int i = l; i < LH; i += 32) {
            float v = (my[2 * i] + my[2 * i + 1] + my[2 * i + 2]) * (1.0f / 3.0f);
            g_h[(b * NC + c) * LH + i] = v;
        }
#pragma unroll
        for (int off = 16; off > 0; off >>= 1) {
            s  += __shfl_down_sync(0xffffffffu, s, off);
            sq += __shfl_down_sync(0xffffffffu, sq, off);
        }
        if (l == 0) { g_psA[c * BATCH + b] = s; g_psqA[c * BATCH + b] = sq; }
        __syncwarp();
    }
}

// ---------------- 3. BN1 finalize ---------------------------------------------------
__global__ void __launch_bounds__(256) k_fin1() {
    int c = blockIdx.x, t = threadIdx.x;
    float s = 0.0f, sq = 0.0f;
    for (int i = t; i < BATCH; i += 256) { s += g_psA[c * BATCH + i]; sq += g_psqA[c * BATCH + i]; }
    __shared__ float ss[256], ssq[256];
    ss[t] = s; ssq[t] = sq;
    __syncthreads();
    for (int o = 128; o > 0; o >>= 1) {
        if (t < o) { ss[t] += ss[t + o]; ssq[t] += ssq[t + o]; }
        __syncthreads();
    }
    if (t == 0) {
        float n = (float)BATCH * (float)LPRE;
        float m = ss[0] / n;
        float v = ssq[0] / n - m * m;
        g_mean1[c] = m;
        g_rstd1[c] = rsqrtf(v + 1e-5f);
    }
}

// ---------------- 4. both branches stage1 (vectorized) ------------------------------
__global__ void __launch_bounds__(256) k_branches(
        const float* __restrict__ bn1_g, const float* __restrict__ bn1_b,
        const float* __restrict__ a1_w, const float* __restrict__ a1_b,
        const float* __restrict__ e1_w, const float* __restrict__ e1_b,
        const float* __restrict__ f1_w, const float* __restrict__ f1_b,
        const float* __restrict__ fa_w, const float* __restrict__ fa_b) {
    __shared__ float sh[16 * LH];
    __shared__ float sa0[8][260];
    __shared__ float sa1[8][260];
    int b = blockIdx.x >> 1;
    int c0 = (blockIdx.x & 1) * 16;
    int t = threadIdx.x;
    int l = t & 31, w = t >> 5;

    // load 16 channel rows of h (float4, coalesced)
    {
        const float4* src = (const float4*)&g_h[(b * NC + c0) * LH];
        float4* dst = (float4*)sh;
        for (int i = t; i < 16 * (LH / 4); i += 256) dst[i] = src[i];
    }
    __syncthreads();

    for (int u = 0; u < 2; u++) {
        int cc = c0 + w * 2 + u;
        const float* hrow = &sh[(w * 2 + u) * LH];
        float sc = g_rstd1[cc] * bn1_g[cc];
        float shv = bn1_b[cc] - g_mean1[cc] * sc;

        // folded weights, both branches
        float wA0[8], wB0[8], wA1[8], wB1[8];
        float bA0, bB0, bA1, bB1;
        {
            float sw = 0.0f;
#pragma unroll
            for (int k = 0; k < 8; k++) { float wv = a1_w[cc * 8 + k]; wA0[k] = sc * wv; sw += wv; }
            bA0 = (a1_b[cc] - sw) + shv * sw;                  // Always
#pragma unroll
            for (int k = 0; k < 8; k++) wB0[k] = e1_w[cc * 8 + k];
            bB0 = 1.0f - e1_b[cc];                             // Eventually
        }
        {
            float sw = 0.0f;
#pragma unroll
            for (int k = 0; k < 8; k++) { float wv = f1_w[cc * 8 + k]; wA1[k] = sc * wv; sw += wv; }
            bA1 = (1.0f - f1_b[cc]) + shv * sw;                // Eventually
            float sw2 = 0.0f;
#pragma unroll
            for (int k = 0; k < 8; k++) { float wv = fa_w[cc * 8 + k]; wB1[k] = wv; sw2 += wv; }
            bB1 = fa_b[cc] - sw2;                              // Always
        }

        // conv1 (stride 2) -> 257, both branches share h window loads
#pragma unroll
        for (int j = 0; j < 2; j++) {
            int o0 = 4 * l + 128 * j;
            int base = 2 * o0;
            float hw[16];
#pragma unroll
            for (int q = 0; q < 4; q++) {
                float4 v = *(const float4*)&hrow[base + 4 * q];
                hw[4 * q + 0] = v.x; hw[4 * q + 1] = v.y; hw[4 * q + 2] = v.z; hw[4 * q + 3] = v.w;
            }
            float4 r0v, r1v;
            float* p0 = (float*)&r0v;
            float* p1 = (float*)&r1v;
#pragma unroll
            for (int q = 0; q < 4; q++) {
                float a0 = bA0, a1v = bA1;
#pragma unroll
                for (int k = 0; k < 8; k++) {
                    float hv = hw[2 * q + k];
                    a0  += hv * wA0[k];
                    a1v += hv * wA1[k];
                }
                p0[q] = fmaxf(a0, 0.0f);
                p1[q] = fmaxf(a1v, 0.0f);
            }
            *(float4*)&sa0[w][o0] = r0v;
            *(float4*)&sa1[w][o0] = r1v;
        }
        if (l == 0) {   // tail output 256
            float a0 = bA0, a1v = bA1;
#pragma unroll
            for (int k = 0; k < 8; k++) {
                float hv = hrow[512 + k];
                a0  += hv * wA0[k];
                a1v += hv * wA1[k];
            }
            sa0[w][256] = fmaxf(a0, 0.0f);
            sa1[w][256] = fmaxf(a1v, 0.0f);
        }
        __syncwarp();

        // conv2 (stride 2, 125 outs) + maxpool(4,4) fused in registers
#pragma unroll
        for (int br = 0; br < 2; br++) {
            const float* sa = (br == 0) ? sa0[w] : sa1[w];
            const float* w2 = (br == 0) ? wB0 : wB1;
            float b2 = (br == 0) ? bB0 : bB1;
            float s = 0.0f, sq = 0.0f;
            if (l < LP) {
                float aw[16];
#pragma unroll
                for (int q = 0; q < 4; q++) {
                    float4 v = *(const float4*)&sa[8 * l + 4 * q];
                    aw[4 * q + 0] = v.x; aw[4 * q + 1] = v.y; aw[4 * q + 2] = v.z; aw[4 * q + 3] = v.w;
                }
                float mx = 0.0f;
#pragma unroll
                for (int q = 0; q < 4; q++) {
                    float a = b2;
#pragma unroll
                    for (int k = 0; k < 8; k++) a += aw[2 * q + k] * w2[k];
                    a = fmaxf(a, 0.0f);
                    mx = (q == 0) ? a : fmaxf(mx, a);
                }
                float* pout = (br == 0) ? g_p1 : g_p2;
                pout[(b * NC + cc) * LP + l] = mx;
                s = mx; sq = mx * mx;
            }
#pragma unroll
            for (int off = 16; off > 0; off >>= 1) {
                s  += __shfl_down_sync(0xffffffffu, s, off);
                sq += __shfl_down_sync(0xffffffffu, sq, off);
            }
            if (l == 0) {
                g_ps2[(br * NC + cc) * BATCH + b] = s;
                g_psq2[(br * NC + cc) * BATCH + b] = sq;
            }
        }
        __syncwarp();
    }
}

// ---------------- 5. BN2/BN3 finalize -----------------------------------------------
__global__ void __launch_bounds__(256) k_fin2() {
    int bc = blockIdx.x;
    int t = threadIdx.x;
    float s = 0.0f, sq = 0.0f;
    for (int i = t; i < BATCH; i += 256) { s += g_ps2[bc * BATCH + i]; sq += g_psq2[bc * BATCH + i]; }
    __shared__ float ss[256], ssq[256];
    ss[t] = s; ssq[t] = sq;
    __syncthreads();
    for (int o = 128; o > 0; o >>= 1) {
        if (t < o) { ss[t] += ss[t + o]; ssq[t] += ssq[t + o]; }
        __syncthreads();
    }
    if (t == 0) {
        float n = (float)BATCH * (float)LP;
        float m = ss[0] / n;
        float v = ssq[0] / n - m * m;
        int br = bc >> 5, c = bc & 31;
        if (br == 0) { g_mean2[c] = m; g_rstd2[c] = rsqrtf(v + 1e-5f); }
        else         { g_mean3[c] = m; g_rstd3[c] = rsqrtf(v + 1e-5f); }
    }
}

// ---------------- 6. BN + final eventually -> z -------------------------------------
__global__ void __launch_bounds__(256) k_stage2(int branch,
                                                const float* __restrict__ g,
                                                const float* __restrict__ be,
                                                const float* __restrict__ w,
                                                const float* __restrict__ bb) {
    int bc = blockIdx.x * blockDim.x + threadIdx.x;
    if (bc >= BATCH * NC) return;
    int b = bc >> 5, c = bc & (NC - 1);
    const float* p;
    const float* meanv;
    const float* rstdv;
    int zbase;
    if (branch == 0) { p = g_p1; meanv = g_mean2; rstdv = g_rstd2; zbase = 0; }
    else             { p = g_p2; meanv = g_mean3; rstdv = g_rstd3; zbase = 384; }
    float sc = rstdv[c] * g[c];
    float sh = be[c] - meanv[c] * sc;
    float wv[8];
    float sw = 0.0f;
#pragma unroll
    for (int k = 0; k < 8; k++) { wv[k] = w[c * 8 + k] * sc; sw += w[c * 8 + k]; }
    float bias = (1.0f - bb[c]) + sh * sw;
    float y[LP];
    const float* row = &p[bc * LP];
#pragma unroll
    for (int i = 0; i < LP; i++) y[i] = row[i];
#pragma unroll
    for (int j = 0; j < LZ; j++) {
        float acc = bias;
#pragma unroll
        for (int k = 0; k < 8; k++) acc += y[2 * j + k] * wv[k];
        g_z[b * 768 + zbase + c * LZ + j] = fmaxf(acc, 0.0f);
    }
}

// ---------------- 7. TF32 split-precision tensor-core GEMM + bias + relu ------------
// C(1024,N) = relu(A(1024,K) @ W(K,N) + bias). 128x64 block tile, m16n8k8 mma,
// A,B split into tf32 hi/lo; 3 passes (hi*hi + hi*lo + lo*hi) -> ~2^-22 error.
__device__ __forceinline__ void tf32split(float x, uint32_t& hi, uint32_t& lo) {
    uint32_t h;
    asm("cvt.rna.tf32.f32 %0, %1;" : "=r"(h) : "f"(x));
    hi = h;
    lo = __float_as_uint(x - __uint_as_float(h));
}
__device__ __forceinline__ void mma8(float* c, const uint32_t* a, const uint32_t* b) {
    asm volatile("mma.sync.aligned.m16n8k8.row.col.f32.tf32.tf32.f32 "
                 "{%0,%1,%2,%3},{%4,%5,%6,%7},{%8,%9},{%0,%1,%2,%3};"
                 : "+f"(c[0]), "+f"(c[1]), "+f"(c[2]), "+f"(c[3])
                 : "r"(a[0]), "r"(a[1]), "r"(a[2]), "r"(a[3]), "r"(b[0]), "r"(b[1]));
}

__global__ void __launch_bounds__(256) k_gemm_mma(int stage,
                                                  const float* __restrict__ W,
                                                  const float* __restrict__ bias,
                                                  int K, int N) {
    const float* A;
    float* C;
    if (stage == 0)      { A = g_z;  C = g_z1; }
    else if (stage == 1) { A = g_z1; C = g_z2; }
    else                 { A = g_z2; C = g_z3; }

    __shared__ float As[128 * 36];   // [m][k], stride 36 -> conflict-free frag loads
    __shared__ float Bs[32 * 72];    // [k][n], stride 72 -> conflict-free frag loads
    int tid = threadIdx.x;
    int lane = tid & 31, wid = tid >> 5;
    int wm = wid >> 1, wn = wid & 1;           // 4x2 warp grid, warp tile 32x32
    int m0 = blockIdx.y * 128, n0 = blockIdx.x * 64;

    float acc[2][4][4];
#pragma unroll
    for (int i = 0; i < 2; i++)
#pragma unroll
        for (int j = 0; j < 4; j++)
#pragma unroll
            for (int q = 0; q < 4; q++) acc[i][j][q] = 0.0f;

    for (int k0 = 0; k0 < K; k0 += 32) {
#pragma unroll
        for (int i = 0; i < 4; i++) {
            int idx = tid + 256 * i;
            int m = idx >> 3, k4 = (idx & 7) << 2;
            float4 v = *(const float4*)(A + (m0 + m) * K + k0 + k4);
            *(float4*)&As[m * 36 + k4] = v;
        }
#pragma unroll
        for (int i = 0; i < 2; i++) {
            int idx = tid + 256 * i;
            int k = idx >> 4, n4 = (idx & 15) << 2;
            *(float4*)&Bs[k * 72 + n4] = *(const float4*)(W + (k0 + k) * N + n0 + n4);
        }
        __syncthreads();
#pragma unroll
        for (int ks = 0; ks < 4; ks++) {
            int kk = ks * 8 + (lane & 3);
            int r0 = wm * 32 + (lane >> 2);
            uint32_t ahi[2][4], alo[2][4];
#pragma unroll
            for (int tm = 0; tm < 2; tm++) {
                int row = r0 + tm * 16;
                tf32split(As[row * 36 + kk],           ahi[tm][0], alo[tm][0]);
                tf32split(As[(row + 8) * 36 + kk],     ahi[tm][1], alo[tm][1]);
                tf32split(As[row * 36 + kk + 4],       ahi[tm][2], alo[tm][2]);
                tf32split(As[(row + 8) * 36 + kk + 4], ahi[tm][3], alo[tm][3]);
            }
            uint32_t bhi[4][2], blo[4][2];
            int cb = wn * 32 + (lane >> 2);
#pragma unroll
            for (int tn = 0; tn < 4; tn++) {
                tf32split(Bs[kk * 72 + cb + tn * 8],       bhi[tn][0], blo[tn][0]);
                tf32split(Bs[(kk + 4) * 72 + cb + tn * 8], bhi[tn][1], blo[tn][1]);
            }
#pragma unroll
            for (int tm = 0; tm < 2; tm++)
#pragma unroll
                for (int tn = 0; tn < 4; tn++) {
                    mma8(acc[tm][tn], ahi[tm], bhi[tn]);
                    mma8(acc[tm][tn], ahi[tm], blo[tn]);
                    mma8(acc[tm][tn], alo[tm], bhi[tn]);
                }
        }
        __syncthreads();
    }

    // epilogue: bias + relu
#pragma unroll
    for (int tm = 0; tm < 2; tm++) {
        int row = m0 + wm * 32 + tm * 16 + (lane >> 2);
#pragma unroll
        for (int tn = 0; tn < 4; tn++) {
            int col = n0 + wn * 32 + tn * 8 + (lane & 3) * 2;
            float bv0 = bias[col], bv1 = bias[col + 1];
            C[row * N + col]           = fmaxf(acc[tm][tn][0] + bv0, 0.0f);
            C[row * N + col + 1]       = fmaxf(acc[tm][tn][1] + bv1, 0.0f);
            C[(row + 8) * N + col]     = fmaxf(acc[tm][tn][2] + bv0, 0.0f);
            C[(row + 8) * N + col + 1] = fmaxf(acc[tm][tn][3] + bv1, 0.0f);
        }
    }
}

// ---------------- 8. final tiny GEMM (K=128, N=10) ----------------------------------
__global__ void __launch_bounds__(256) k_gemm4(const float* __restrict__ W,
                                               const float* __restrict__ bias,
                                               float* __restrict__ out) {
    __shared__ float sw[128 * 10];
    __shared__ float sb[10];
    int t = threadIdx.x;
    for (int i = t; i < 1280; i += 256) sw[i] = W[i];
    if (t < 10) sb[t] = bias[t];
    __syncthreads();
    int idx = blockIdx.x * 256 + t;
    if (idx >= BATCH * 10) return;
    int m = idx / 10, n = idx % 10;
    const float* a = &g_z3[m * 128];
    float acc = sb[n];
#pragma unroll 16
    for (int k = 0; k < 128; k++) acc += a[k] * sw[k * 10 + n];
    out[idx] = fmaxf(acc, 0.0f);
}

// ---------------- host ---------------------------------------------------------------
extern "C" void kernel_launch(void* const* d_in, const int* in_sizes, int n_in,
                              void* d_out, int out_size) {
    const float* x       = (const float*)d_in[0];
    const float* la_a    = (const float*)d_in[1];
    const float* la_b    = (const float*)d_in[2];
    const float* la_bias = (const float*)d_in[3];
    const float* bn1_g   = (const float*)d_in[4];
    const float* bn1_b   = (const float*)d_in[5];
    const float* a1_w = (const float*)d_in[6];
    const float* a1_b = (const float*)d_in[7];
    const float* e1_w = (const float*)d_in[8];
    const float* e1_b = (const float*)d_in[9];
    const float* bn2_g = (const float*)d_in[10];
    const float* bn2_b = (const float*)d_in[11];
    const float* e2_w = (const float*)d_in[12];
    const float* e2_b = (const float*)d_in[13];
    const float* f1_w = (const float*)d_in[14];
    const float* f1_b = (const float*)d_in[15];
    const float* fa_w = (const float*)d_in[16];
    const float* fa_b = (const float*)d_in[17];
    const float* bn3_g = (const float*)d_in[18];
    const float* bn3_b = (const float*)d_in[19];
    const float* f2_w = (const float*)d_in[20];
    const float* f2_b = (const float*)d_in[21];
    const float* w1 = (const float*)d_in[22];
    const float* b1 = (const float*)d_in[23];
    const float* w2 = (const float*)d_in[24];
    const float* b2 = (const float*)d_in[25];
    const float* w3 = (const float*)d_in[26];
    const float* b3 = (const float*)d_in[27];
    const float* w4 = (const float*)d_in[28];
    const float* b4 = (const float*)d_in[29];
    float* out = (float*)d_out;

    k_filt<<<1, 512>>>(la_a, la_b);
    k_convfuse<<<BATCH, 256>>>(x, la_bias);
    k_fin1<<<NC, 256>>>();
    k_branches<<<BATCH * 2, 256>>>(bn1_g, bn1_b, a1_w, a1_b, e1_w, e1_b,
                                   f1_w, f1_b, fa_w, fa_b);
    k_fin2<<<2 * NC, 256>>>();
    k_stage2<<<(BATCH * NC + 255) / 256, 256>>>(0, bn2_g, bn2_b, e2_w, e2_b);
    k_stage2<<<(BATCH * NC + 255) / 256, 256>>>(1, bn3_g, bn3_b, f2_w, f2_b);

    k_gemm_mma<<<dim3(16, 8), 256>>>(0, w1, b1, 768, 1024);
    k_gemm_mma<<<dim3(8, 8),  256>>>(1, w2, b2, 1024, 512);
    k_gemm_mma<<<dim3(2, 8),  256>>>(2, w3, b3, 512, 128);
    k_gemm4<<<40, 256>>>(w4, b4, out);
}